// round 15
// baseline (speedup 1.0000x reference)
#include <cuda_runtime.h>
#include <cuda_bf16.h>
#include <math.h>

#define NRAYS 1024
#define NSAMP 447
#define NPTS  (NRAYS*NSAMP)
#define NVOX  262144          // 64^3
#define NPAIR (NVOX/2)
#define NFINE 2097152         // 128^3
#define ACT_SHIFT (-9.210240366975184f)
#define BN_SCALE  (0.9999950000374997f)

typedef unsigned long long u64;
typedef unsigned int u32;

// ---------------- scratch (channel-major bf16x2 words: {voxA,voxB}) ----------------
__device__ u32 g_c1[64*NPAIR];    // x1 activations
__device__ u32 g_c2[64*NPAIR];    // x2 activations
__device__ u32 g_cg[16*NPAIR];    // bf16 copy of grid
__device__ float4 g_feat[(size_t)NFINE*4];
__device__ float  g_up0[NFINE];
__device__ float4 g_norm[NFINE];
__device__ float4 g_rgba[NPTS];
__device__ float4 g_nd4[NPTS];
__device__ float4 g_ns4[NPTS];
__device__ float  g_depth[NPTS];

// ---------------- f32x2 helpers ----------------
__device__ __forceinline__ u64 pk(float lo, float hi){
    u64 r; asm("mov.b64 %0,{%1,%2};" : "=l"(r) : "f"(lo), "f"(hi)); return r;
}
__device__ __forceinline__ u64 pk1(float v){ return pk(v,v); }
__device__ __forceinline__ float2 upk(u64 p){
    float2 r; asm("mov.b64 {%0,%1},%2;" : "=f"(r.x), "=f"(r.y) : "l"(p)); return r;
}
__device__ __forceinline__ void fma2(u64 &d, u64 a, u64 b){
    asm("fma.rn.f32x2 %0, %1, %2, %0;" : "+l"(d) : "l"(a), "l"(b));
}
__device__ __forceinline__ u32 bpack(float lo, float hi){
    __nv_bfloat162 h=__floats2bfloat162_rn(lo,hi); return *(u32*)&h;
}
// ---------------- cp.async ----------------
__device__ __forceinline__ void cpa16(u32 s, const void* g){
    asm volatile("cp.async.cg.shared.global [%0], [%1], 16;" :: "r"(s), "l"(g));
}
#define CPA_COMMIT() asm volatile("cp.async.commit_group;")
#define CPA_WAIT1()  asm volatile("cp.async.wait_group 1;" ::: "memory")
#define CPA_WAIT0()  asm volatile("cp.async.wait_group 0;" ::: "memory")
__device__ __forceinline__ u32 smem_u32(const void* p){
    u32 a; asm("{ .reg .u64 t; cvta.to.shared.u64 t, %1; cvt.u32.u64 %0, t; }" : "=r"(a) : "l"(p));
    return a;
}

// =============== K0: dummy (keeps ncu capture position) ===============
__global__ void k_dummy() {}

// =============== K1: x1 = prelu(bn(conv16->64)) -> g_c1 channel-major (+grid->g_cg) ===============
#define CONVJ16(SWP) { \
    _Pragma("unroll") for(int o2=0;o2<16;o2++){ \
        ulonglong2 W=(SWP)[o2]; \
        fma2(aA[o2],A0,W.x); fma2(aA[o2],A1,W.y); \
        fma2(aB[o2],B0,W.x); fma2(aB[o2],B1,W.y); } }

__global__ void __launch_bounds__(256,2) k_x1(const float* __restrict__ grid,
    const float* __restrict__ w, const float* __restrict__ b,
    const float* __restrict__ bg, const float* __restrict__ bb,
    const float* __restrict__ pa)
{
    __shared__ ulonglong2 sw[8*16];
    __shared__ __align__(16) float sin_[16*512];
    int t=threadIdx.x, ob=blockIdx.x, r0=ob*32;
    for(int i=t;i<8*16;i+=256){
        int cp=i>>4, o2=i&15;
        int ra=r0+2*o2, rb=ra+1;
        sw[i]=make_ulonglong2( pk(w[ra*16+2*cp],   w[rb*16+2*cp]),
                               pk(w[ra*16+2*cp+1], w[rb*16+2*cp+1]) );
    }
    size_t vbase=(size_t)blockIdx.y*512;
    u32 sb=smem_u32(sin_);
    for(int f=t; f<16*128; f+=256){
        int ch=f>>7, i16=f&127;
        cpa16(sb + ch*2048 + i16*16, grid + (size_t)ch*NVOX + vbase + i16*4);
    }
    CPA_COMMIT(); CPA_WAIT0();
    __syncthreads();

    int gid=blockIdx.y*256+t;
    u64 aA[16], aB[16];
#pragma unroll
    for(int o2=0;o2<16;o2++){ u64 bi=pk(__ldg(b+r0+2*o2),__ldg(b+r0+2*o2+1)); aA[o2]=bi; aB[o2]=bi; }
#pragma unroll
    for(int cp=0;cp<8;cp++){
        float2 i0=*(const float2*)(sin_+(2*cp  )*512+2*t);
        float2 i1=*(const float2*)(sin_+(2*cp+1)*512+2*t);
        if(ob==0){
            g_cg[(size_t)(2*cp  )*NPAIR+gid]=bpack(i0.x,i0.y);
            g_cg[(size_t)(2*cp+1)*NPAIR+gid]=bpack(i1.x,i1.y);
        }
        u64 A0=pk1(i0.x), A1=pk1(i1.x), B0=pk1(i0.y), B1=pk1(i1.y);
        CONVJ16(sw+cp*16);
    }
#pragma unroll
    for(int o2=0;o2<16;o2++){
        float2 yA=upk(aA[o2]), yB=upk(aB[o2]);
        int c0=r0+2*o2, c1=c0+1;
        float s0=BN_SCALE*__ldg(bg+c0), t0=__ldg(bb+c0), p0=__ldg(pa+c0);
        float s1=BN_SCALE*__ldg(bg+c1), t1=__ldg(bb+c1), p1=__ldg(pa+c1);
        float a0=yA.x*s0+t0, b0v=yB.x*s0+t0;
        float a1=yA.y*s1+t1, b1v=yB.y*s1+t1;
        a0=(a0>=0.f)?a0:p0*a0; b0v=(b0v>=0.f)?b0v:p0*b0v;
        a1=(a1>=0.f)?a1:p1*a1; b1v=(b1v>=0.f)?b1v:p1*b1v;
        g_c1[(size_t)c0*NPAIR+gid]=bpack(a0,b0v);
        g_c1[(size_t)c1*NPAIR+gid]=bpack(a1,b1v);
    }
}

// ---- shared conv core: 4 voxels x 8 out-pairs per thread ----
// acc[o2][v]: v0=word0.lo v1=word0.hi v2=word1.lo v3=word1.hi
#define CONV_J4(SWP, qa, qb) { \
    u64 X0[4], X1[4]; \
    X0[0]=pk1(__uint_as_float((qa).x<<16)); X0[1]=pk1(__uint_as_float((qa).x&0xffff0000u)); \
    X0[2]=pk1(__uint_as_float((qa).y<<16)); X0[3]=pk1(__uint_as_float((qa).y&0xffff0000u)); \
    X1[0]=pk1(__uint_as_float((qb).x<<16)); X1[1]=pk1(__uint_as_float((qb).x&0xffff0000u)); \
    X1[2]=pk1(__uint_as_float((qb).y<<16)); X1[3]=pk1(__uint_as_float((qb).y&0xffff0000u)); \
    _Pragma("unroll") for(int o2=0;o2<8;o2++){ \
        ulonglong2 W=(SWP)[o2]; \
        _Pragma("unroll") for(int v=0;v<4;v++){ \
            fma2(acc[o2][v],X0[v],W.x); fma2(acc[o2][v],X1[v],W.y); } } }

// =============== K2: x2 conv 80->64; CTA = 16 out-ch x 1024 voxels ===============
__global__ void __launch_bounds__(256,2) k_x2(
    const float* __restrict__ w, const float* __restrict__ b,
    const float* __restrict__ bg, const float* __restrict__ bb,
    const float* __restrict__ pa)
{
    __shared__ ulonglong2 sw[40*8];                // 5 KB
    __shared__ __align__(16) u32 sbuf[3][4*512];   // 24 KB
    int t=threadIdx.x, ob=blockIdx.x, r0=ob*16;
    for(int i=t;i<40*8;i+=256){
        int cp=i>>3, o2=i&7;
        int ra=r0+2*o2, rb=ra+1;
        sw[i]=make_ulonglong2( pk(w[ra*80+2*cp],   w[rb*80+2*cp]),
                               pk(w[ra*80+2*cp+1], w[rb*80+2*cp+1]) );
    }
    size_t pbase=(size_t)blockIdx.y*512;
    u32 sb[3];
#pragma unroll
    for(int s=0;s<3;s++) sb[s]=smem_u32(sbuf[s]);

    #define X2_LOAD(c) { int bi=(c)%3; \
        for(int f=t; f<512; f+=256){ \
            int chl=f>>7, i=f&127; \
            int g=(c)*4+chl; \
            const u32* S=(g<64)?(g_c1+(size_t)g*NPAIR):(g_cg+(size_t)(g-64)*NPAIR); \
            cpa16(sb[bi]+chl*2048+i*16, S+pbase+i*4); \
        } CPA_COMMIT(); }

    X2_LOAD(0); X2_LOAD(1);

    u64 acc[8][4];
#pragma unroll
    for(int o2=0;o2<8;o2++){
        u64 bi=pk(__ldg(b+r0+2*o2),__ldg(b+r0+2*o2+1));
#pragma unroll
        for(int v=0;v<4;v++) acc[o2][v]=bi;
    }

    for(int c=0;c<20;c++){
        CPA_WAIT1();
        __syncthreads();
        if(c+2<20){ X2_LOAD(c+2); } else { CPA_COMMIT(); }
        const u32* buf=sbuf[c%3];
#pragma unroll
        for(int j=0;j<2;j++){
            uint2 qa=*(const uint2*)&buf[(2*j  )*512+2*t];
            uint2 qb=*(const uint2*)&buf[(2*j+1)*512+2*t];
            CONV_J4(sw+(c*2+j)*8, qa, qb);
        }
    }
    size_t pw=pbase+2*t;
#pragma unroll
    for(int o2=0;o2<8;o2++){
        int c0=r0+2*o2, c1=c0+1;
        float s0=BN_SCALE*__ldg(bg+c0), t0=__ldg(bb+c0), p0=__ldg(pa+c0);
        float s1=BN_SCALE*__ldg(bg+c1), t1=__ldg(bb+c1), p1=__ldg(pa+c1);
        float a0[4], a1[4];
#pragma unroll
        for(int v=0;v<4;v++){
            float2 f2=upk(acc[o2][v]);
            float y0=f2.x*s0+t0, y1=f2.y*s1+t1;
            a0[v]=(y0>=0.f)?y0:p0*y0;
            a1[v]=(y1>=0.f)?y1:p1*y1;
        }
        *(uint2*)&g_c2[(size_t)c0*NPAIR+pw]=make_uint2(bpack(a0[0],a0[1]),bpack(a0[2],a0[3]));
        *(uint2*)&g_c2[(size_t)c1*NPAIR+pw]=make_uint2(bpack(a1[0],a1[1]),bpack(a1[2],a1[3]));
    }
}

// =============== K3: x3 conv 144->128; CTA = 16 out-ch (2 latents) x 1024 voxels ===============
__global__ void __launch_bounds__(256,2) k_x3(
    const float* __restrict__ w, const float* __restrict__ b)
{
    __shared__ ulonglong2 sw[72*8];                // 9 KB
    __shared__ __align__(16) u32 sbuf[3][4*512];   // 24 KB
    int t=threadIdx.x, ob=blockIdx.x, r0=ob*16;    // latents 2ob, 2ob+1
    for(int i=t;i<72*8;i+=256){
        int cp=i>>3, o2=i&7;
        int ra=r0+2*o2, rb=ra+1;
        sw[i]=make_ulonglong2( pk(w[ra*144+2*cp],   w[rb*144+2*cp]),
                               pk(w[ra*144+2*cp+1], w[rb*144+2*cp+1]) );
    }
    size_t pbase=(size_t)blockIdx.y*512;
    u32 sb[3];
#pragma unroll
    for(int s=0;s<3;s++) sb[s]=smem_u32(sbuf[s]);

    #define X3_LOAD(c) { int bi=(c)%3; \
        for(int f=t; f<512; f+=256){ \
            int chl=f>>7, i=f&127; \
            int g=(c)*4+chl; \
            const u32* S=(g<64)?(g_c1+(size_t)g*NPAIR) \
                        :(g<128)?(g_c2+(size_t)(g-64)*NPAIR) \
                        :(g_cg+(size_t)(g-128)*NPAIR); \
            cpa16(sb[bi]+chl*2048+i*16, S+pbase+i*4); \
        } CPA_COMMIT(); }

    X3_LOAD(0); X3_LOAD(1);

    u64 acc[8][4];
#pragma unroll
    for(int o2=0;o2<8;o2++){
        u64 bi=pk(__ldg(b+r0+2*o2),__ldg(b+r0+2*o2+1));
#pragma unroll
        for(int v=0;v<4;v++) acc[o2][v]=bi;
    }

    for(int c=0;c<36;c++){
        CPA_WAIT1();
        __syncthreads();
        if(c+2<36){ X3_LOAD(c+2); } else { CPA_COMMIT(); }
        const u32* buf=sbuf[c%3];
#pragma unroll
        for(int j=0;j<2;j++){
            uint2 qa=*(const uint2*)&buf[(2*j  )*512+2*t];
            uint2 qb=*(const uint2*)&buf[(2*j+1)*512+2*t];
            CONV_J4(sw+(c*2+j)*8, qa, qb);
        }
    }
    // epilogue: ch k=2o2+comp (0..15): latent l=2ob+(k>>3), sub s=k&7
    // g_feat float-index = vox*128 + s*16 + l -> float2 at (vox*64 + s*8 + ob)
    float chv[16][4];
#pragma unroll
    for(int o2=0;o2<8;o2++)
#pragma unroll
    for(int v=0;v<4;v++){
        float2 f2=upk(acc[o2][v]);
        chv[2*o2][v]=f2.x; chv[2*o2+1][v]=f2.y;
    }
    float2* gf2=(float2*)g_feat;
#pragma unroll
    for(int v=0;v<4;v++){
        int pairw=(int)(pbase+2*t+(v>>1));
        int vox=2*pairw+(v&1);
        int x=vox>>12, y=(vox>>6)&63, z=vox&63;
#pragma unroll
        for(int s=0;s<8;s++){
            gf2[(size_t)vox*64 + s*8 + ob]=make_float2(chv[s][v], chv[8+s][v]);
            if(ob==0){
                int X=2*x+((s>>2)&1), Y=2*y+((s>>1)&1), Z=2*z+(s&1);
                g_up0[((size_t)X*128+Y)*128+Z]=chv[s][v];
            }
        }
    }
}

// =============== K4: separable Sobel -> normals ===============
__global__ void __launch_bounds__(256) k_sobel()
{
    __shared__ float sm[1728];
    __shared__ float A[1152], Bz[1152];
    __shared__ float C[768], D[768], E[768];
    const float HH[5]={1.f,4.f,6.f,4.f,1.f};
    const float HD[5]={-1.f,-2.f,0.f,2.f,1.f};
    int bx=blockIdx.x*8, by=blockIdx.y*8, bz=blockIdx.z*8;
    int t=threadIdx.x;
    for(int i=t;i<1728;i+=256){
        int a=i/144, b=(i/12)%12, c=i%12;
        int X=bx+a-2, Y=by+b-2, Z=bz+c-2;
        float val=0.f;
        if(X>=0&&X<128&&Y>=0&&Y<128&&Z>=0&&Z<128) val=g_up0[((size_t)X*128+Y)*128+Z];
        sm[i]=val;
    }
    __syncthreads();
    for(int i=t;i<1152;i+=256){
        int a=i/96, b=(i/8)%12, zo=i&7;
        const float* base=&sm[(a*12+b)*12+zo];
        float s=0.f,d=0.f;
#pragma unroll
        for(int k=0;k<5;k++){ float v=base[k]; s=fmaf(HH[k],v,s); d=fmaf(HD[k],v,d); }
        A[i]=s; Bz[i]=d;
    }
    __syncthreads();
    for(int i=t;i<768;i+=256){
        int a=i>>6, yo=(i>>3)&7, zo=i&7;
        float c=0.f,dd=0.f,e=0.f;
#pragma unroll
        for(int j=0;j<5;j++){
            int idx=(a*12+yo+j)*8+zo;
            float av=A[idx], bv=Bz[idx];
            c=fmaf(HH[j],av,c); dd=fmaf(HD[j],av,dd); e=fmaf(HH[j],bv,e);
        }
        C[i]=c; D[i]=dd; E[i]=e;
    }
    __syncthreads();
    for(int i=t;i<512;i+=256){
        int xo=i>>6, yo=(i>>3)&7, zo=i&7;
        float sx=0.f,sy=0.f,sz=0.f;
#pragma unroll
        for(int k=0;k<5;k++){
            int idx=((xo+k)*8+yo)*8+zo;
            sx=fmaf(HD[k],C[idx],sx); sy=fmaf(HH[k],D[idx],sy); sz=fmaf(HH[k],E[idx],sz);
        }
        float l=sqrtf(sx*sx+sy*sy+sz*sz);
        float r=1.f/fmaxf(l,1e-12f);
        g_norm[(((size_t)(bx+xo)*128)+(by+yo))*128+(bz+zo)] =
            make_float4(-sx*r,-sy*r,-sz*r,0.f);
    }
}

// =============== K5: per-sample point shading ===============
#define FEED0(cp, v0, v1) { u64 x0=pk1(v0), x1=pk1(v1); \
    _Pragma("unroll") for(int o2=0;o2<32;o2++){ ulonglong2 W=SW0[(cp)*32+o2]; \
        fma2(h2[o2],x0,W.x); fma2(h2[o2],x1,W.y);} }

__global__ void __launch_bounds__(256) k_pts(
    const float* __restrict__ rays_o, const float* __restrict__ rays_d,
    const float* __restrict__ viewdirs,
    const float* __restrict__ w0,const float* __restrict__ b0,
    const float* __restrict__ w1,const float* __restrict__ b1,
    const float* __restrict__ w2,const float* __restrict__ b2,
    const float* __restrict__ w3,const float* __restrict__ b3)
{
    __shared__ ulonglong2 SW0[27*32];
    __shared__ ulonglong2 SW1[32*32];
    __shared__ ulonglong2 SW2[32*32];
    __shared__ u64 PB0[32], PB1[32], PB2[32];
    __shared__ float SW3[192], PB3[3];
    int t=threadIdx.x;
    for(int i=t;i<27*32;i+=256){ int cp=i>>5,o2=i&31;
        SW0[i]=make_ulonglong2( pk(w0[(2*cp)*64+2*o2],   w0[(2*cp)*64+2*o2+1]),
                                pk(w0[(2*cp+1)*64+2*o2], w0[(2*cp+1)*64+2*o2+1]) ); }
    for(int i=t;i<32*32;i+=256){ int cp=i>>5,o2=i&31;
        SW1[i]=make_ulonglong2( pk(w1[(2*cp)*64+2*o2],   w1[(2*cp)*64+2*o2+1]),
                                pk(w1[(2*cp+1)*64+2*o2], w1[(2*cp+1)*64+2*o2+1]) );
        SW2[i]=make_ulonglong2( pk(w2[(2*cp)*64+2*o2],   w2[(2*cp)*64+2*o2+1]),
                                pk(w2[(2*cp+1)*64+2*o2], w2[(2*cp+1)*64+2*o2+1]) ); }
    if(t<32){ PB0[t]=pk(b0[2*t],b0[2*t+1]); PB1[t]=pk(b1[2*t],b1[2*t+1]); PB2[t]=pk(b2[2*t],b2[2*t+1]); }
    for(int i=t;i<192;i+=256) SW3[i]=w3[i];
    if(t<3) PB3[t]=b3[t];
    __syncthreads();

    int tid = blockIdx.x*256+t;
    int ray = tid/NSAMP, s = tid - ray*NSAMP;
    float ox=rays_o[ray*3+0], oy=rays_o[ray*3+1], oz=rays_o[ray*3+2];
    float dx=rays_d[ray*3+0], dy=rays_d[ray*3+1], dz=rays_d[ray*3+2];

    float ex=(dx==0.f)?1e-6f:dx, ey=(dy==0.f)?1e-6f:dy, ez=(dz==0.f)?1e-6f:dz;
    float rax=(1.f-ox)/ex, rbx=(-1.f-ox)/ex;
    float ray_=(1.f-oy)/ey, rby=(-1.f-oy)/ey;
    float raz=(1.f-oz)/ez, rbz=(-1.f-oz)/ez;
    float tmin=fmaxf(fmaxf(fminf(rax,rbx),fminf(ray_,rby)),fminf(raz,rbz));
    float tmax=fminf(fminf(fmaxf(rax,rbx),fmaxf(ray_,rby)),fmaxf(raz,rbz));
    tmin=fminf(fmaxf(tmin,0.2f),6.f);
    tmax=fminf(fmaxf(tmax,0.2f),6.f);
    bool maskray = (tmax<=tmin);
    float dnorm=sqrtf(dx*dx+dy*dy+dz*dz);
    float interpx = tmin + (0.015625f*(float)s)/dnorm;
    float px=ox+dx*interpx, py=oy+dy*interpx, pz=oz+dz*interpx;
    g_depth[tid]=dnorm*interpx;

    bool inside = !maskray && !(px<-1.f||px>1.f) && !(py<-1.f||py>1.f) && !(pz<-1.f||pz>1.f);
    if(!inside){
        float4 z4=make_float4(0.f,0.f,0.f,0.f);
        g_rgba[tid]=z4; g_nd4[tid]=z4; g_ns4[tid]=z4;
        return;
    }

    float u0=fminf(fmaxf((px+1.f)*63.5f,0.f),127.f);
    float u1=fminf(fmaxf((py+1.f)*63.5f,0.f),127.f);
    float u2=fminf(fmaxf((pz+1.f)*63.5f,0.f),127.f);
    int ix=min((int)floorf(u0),126), iy=min((int)floorf(u1),126), iz=min((int)floorf(u2),126);
    float fx=u0-ix, fy=u1-iy, fz=u2-iz;
    float wx[2]={1.f-fx,fx}, wy[2]={1.f-fy,fy}, wz[2]={1.f-fz,fz};

    float feat[16];
#pragma unroll
    for(int c=0;c<16;c++) feat[c]=0.f;
    float c0a[2][2][2];
    float nx=0,ny=0,nz=0;
#pragma unroll
    for(int a=0;a<2;a++)
#pragma unroll
    for(int b_=0;b_<2;b_++)
#pragma unroll
    for(int c=0;c<2;c++){
        int X=ix+a, Y=iy+b_, Z=iz+c;
        float w = wx[a]*wy[b_]*wz[c];
        size_t coarse = ((size_t)(X>>1)*64+(Y>>1))*64+(Z>>1);
        size_t base4 = (coarse*8 + ((X&1)*4+(Y&1)*2+(Z&1)))*4;
        float4 q0=g_feat[base4+0], q1=g_feat[base4+1], q2=g_feat[base4+2], q3=g_feat[base4+3];
        feat[0]+=w*q0.x; feat[1]+=w*q0.y; feat[2]+=w*q0.z; feat[3]+=w*q0.w;
        feat[4]+=w*q1.x; feat[5]+=w*q1.y; feat[6]+=w*q1.z; feat[7]+=w*q1.w;
        feat[8]+=w*q2.x; feat[9]+=w*q2.y; feat[10]+=w*q2.z; feat[11]+=w*q2.w;
        feat[12]+=w*q3.x; feat[13]+=w*q3.y; feat[14]+=w*q3.z; feat[15]+=w*q3.w;
        c0a[a][b_][c]=q0.x;
        float4 nn = g_norm[((size_t)X*128+Y)*128+Z];
        nx+=w*nn.x; ny+=w*nn.y; nz+=w*nn.z;
    }
    float gx=0,gy=0,gz=0;
#pragma unroll
    for(int b_=0;b_<2;b_++)
#pragma unroll
    for(int c=0;c<2;c++) gx += wy[b_]*wz[c]*(c0a[1][b_][c]-c0a[0][b_][c]);
#pragma unroll
    for(int a=0;a<2;a++)
#pragma unroll
    for(int c=0;c<2;c++) gy += wx[a]*wz[c]*(c0a[a][1][c]-c0a[a][0][c]);
#pragma unroll
    for(int a=0;a<2;a++)
#pragma unroll
    for(int b_=0;b_<2;b_++) gz += wx[a]*wy[b_]*(c0a[a][b_][1]-c0a[a][b_][0]);

    float d0=feat[0];
    float xs=d0+ACT_SHIFT;
    float ex_=expf(xs);
    float sp=log1pf(ex_);
    float alpha=1.f-expf(-sp*0.5f);
    float sig=ex_/(1.f+ex_);
    float k = 0.5f*expf(-0.5f*sp)*sig*63.5f;
    gx*=k; gy*=k; gz*=k;
    float gl=sqrtf(gx*gx+gy*gy+gz*gz);
    float gr=1.f/fmaxf(gl,1e-12f);
    float ndx=-gx*gr, ndy=-gy*gr, ndz=-gz*gr;
    float nl=sqrtf(nx*nx+ny*ny+nz*nz);
    float nr=1.f/fmaxf(nl,1e-12f);
    g_ns4[tid]=make_float4(-nx*nr,-ny*nr,-nz*nr,0.f);
    g_nd4[tid]=make_float4(ndx,ndy,ndz,0.f);

    float vx=viewdirs[ray*3+0], vy=viewdirs[ray*3+1], vz=viewdirs[ray*3+2];
    float dot = -(vx*ndx+vy*ndy+vz*ndz);
    float rx=2.f*dot*ndx+vx, ry=2.f*dot*ndy+vy, rz=2.f*dot*ndz+vz;

    u64 h2[32];
#pragma unroll
    for(int o2=0;o2<32;o2++) h2[o2]=PB0[o2];
#pragma unroll
    for(int cp=0;cp<7;cp++){ FEED0(cp, feat[2*cp+1], feat[2*cp+2]); }
    FEED0(7, feat[15], rx);
    FEED0(8, ry, rz);
#pragma unroll
    for(int q=0;q<6;q++){
        float fr=(float)(1<<q);
        float s0,c0_,s1,c1,s2,c2;
        __sincosf(rx*fr,&s0,&c0_); __sincosf(ry*fr,&s1,&c1); __sincosf(rz*fr,&s2,&c2);
        FEED0(9+3*q,  s0, s1);
        FEED0(10+3*q, s2, c0_);
        FEED0(11+3*q, c1, c2);
    }
    float h[64];
#pragma unroll
    for(int o2=0;o2<32;o2++){ float2 f=upk(h2[o2]); h[2*o2]=fmaxf(f.x,0.f); h[2*o2+1]=fmaxf(f.y,0.f); }

#pragma unroll
    for(int o2=0;o2<32;o2++) h2[o2]=PB1[o2];
#pragma unroll 2
    for(int cp=0;cp<32;cp++){
        u64 x0=pk1(h[2*cp]), x1=pk1(h[2*cp+1]);
#pragma unroll
        for(int o2=0;o2<32;o2++){ ulonglong2 W=SW1[cp*32+o2]; fma2(h2[o2],x0,W.x); fma2(h2[o2],x1,W.y); }
    }
#pragma unroll
    for(int o2=0;o2<32;o2++){ float2 f=upk(h2[o2]); h[2*o2]=fmaxf(f.x,0.f); h[2*o2+1]=fmaxf(f.y,0.f); }

#pragma unroll
    for(int o2=0;o2<32;o2++) h2[o2]=PB2[o2];
#pragma unroll 2
    for(int cp=0;cp<32;cp++){
        u64 x0=pk1(h[2*cp]), x1=pk1(h[2*cp+1]);
#pragma unroll
        for(int o2=0;o2<32;o2++){ ulonglong2 W=SW2[cp*32+o2]; fma2(h2[o2],x0,W.x); fma2(h2[o2],x1,W.y); }
    }
#pragma unroll
    for(int o2=0;o2<32;o2++){ float2 f=upk(h2[o2]); h[2*o2]=fmaxf(f.x,0.f); h[2*o2+1]=fmaxf(f.y,0.f); }

    float r0=PB3[0], r1=PB3[1], r2=PB3[2];
#pragma unroll
    for(int i=0;i<64;i++){
        float hv=h[i];
        r0=fmaf(hv,SW3[i*3+0],r0); r1=fmaf(hv,SW3[i*3+1],r1); r2=fmaf(hv,SW3[i*3+2],r2);
    }
    g_rgba[tid]=make_float4(1.f/(1.f+expf(-r0)), 1.f/(1.f+expf(-r1)),
                            1.f/(1.f+expf(-r2)), alpha);
}

// =============== K6: per-ray volumetric render (warp per ray) ===============
__global__ void __launch_bounds__(256) k_render(float* __restrict__ out)
{
    int warp=(blockIdx.x*blockDim.x+threadIdx.x)>>5;
    int lane=threadIdx.x&31;
    if(warp>=NRAYS) return;
    int base=warp*NSAMP;
    float T=1.f;
    float sr=0,sg=0,sb=0,sd=0,sa=0,n0=0,n1=0,n2=0,m0=0,m1=0,m2=0;
    for(int c=0;c<14;c++){
        int s=c*32+lane;
        bool val=(s<NSAMP);
        int idx=base+(val?s:0);
        float4 rgba = g_rgba[idx];
        float a = val? rgba.w : 0.f;
        float p=fmaxf(1.f-a,1e-10f);
        float incl=p;
#pragma unroll
        for(int off=1;off<32;off<<=1){
            float tt=__shfl_up_sync(0xffffffffu,incl,off);
            if(lane>=off) incl*=tt;
        }
        float excl=__shfl_up_sync(0xffffffffu,incl,1);
        if(lane==0) excl=1.f;
        float w=a*T*excl;
        float4 nd=g_nd4[idx], ns=g_ns4[idx];
        sr=fmaf(w,rgba.x,sr); sg=fmaf(w,rgba.y,sg); sb=fmaf(w,rgba.z,sb);
        sd=fmaf(w,g_depth[idx],sd);  sa+=w;
        n0=fmaf(w,nd.x,n0); n1=fmaf(w,nd.y,n1); n2=fmaf(w,nd.z,n2);
        m0=fmaf(w,ns.x,m0); m1=fmaf(w,ns.y,m1); m2=fmaf(w,ns.z,m2);
        T*=__shfl_sync(0xffffffffu,incl,31);
    }
#pragma unroll
    for(int off=16;off>0;off>>=1){
        sr+=__shfl_xor_sync(0xffffffffu,sr,off); sg+=__shfl_xor_sync(0xffffffffu,sg,off);
        sb+=__shfl_xor_sync(0xffffffffu,sb,off); sd+=__shfl_xor_sync(0xffffffffu,sd,off);
        sa+=__shfl_xor_sync(0xffffffffu,sa,off);
        n0+=__shfl_xor_sync(0xffffffffu,n0,off); n1+=__shfl_xor_sync(0xffffffffu,n1,off);
        n2+=__shfl_xor_sync(0xffffffffu,n2,off);
        m0+=__shfl_xor_sync(0xffffffffu,m0,off); m1+=__shfl_xor_sync(0xffffffffu,m1,off);
        m2+=__shfl_xor_sync(0xffffffffu,m2,off);
    }
    if(lane==0){
        float* o=out+(size_t)warp*12;
        float dm = sd + T*6.f;
        o[0]=sr+T; o[1]=sg+T; o[2]=sb+T;
        o[3]=dm; o[4]=1.f/dm; o[5]=sa;
        o[6]=n0; o[7]=n1; o[8]=n2;
        o[9]=m0; o[10]=m1; o[11]=m2;
    }
}

extern "C" void kernel_launch(void* const* d_in, const int* in_sizes, int n_in,
                              void* d_out, int out_size)
{
    const float* rays_o  =(const float*)d_in[0];
    const float* rays_d  =(const float*)d_in[1];
    const float* viewdirs=(const float*)d_in[2];
    const float* grid    =(const float*)d_in[3];
    const float* c1w=(const float*)d_in[4];  const float* c1b=(const float*)d_in[5];
    const float* bn1g=(const float*)d_in[6]; const float* bn1b=(const float*)d_in[7];
    const float* pr1a=(const float*)d_in[8];
    const float* c2w=(const float*)d_in[9];  const float* c2b=(const float*)d_in[10];
    const float* bn2g=(const float*)d_in[11];const float* bn2b=(const float*)d_in[12];
    const float* pr2a=(const float*)d_in[13];
    const float* c3w=(const float*)d_in[14]; const float* c3b=(const float*)d_in[15];
    const float* w0=(const float*)d_in[16];  const float* b0=(const float*)d_in[17];
    const float* w1=(const float*)d_in[18];  const float* b1=(const float*)d_in[19];
    const float* w2=(const float*)d_in[20];  const float* b2=(const float*)d_in[21];
    const float* w3=(const float*)d_in[22];  const float* b3=(const float*)d_in[23];
    float* out=(float*)d_out;

    k_dummy<<<1,32>>>();
    k_x1<<<dim3(2,512),256>>>(grid,c1w,c1b,bn1g,bn1b,pr1a);
    k_x2<<<dim3(4,256),256>>>(c2w,c2b,bn2g,bn2b,pr2a);
    k_x3<<<dim3(8,256),256>>>(c3w,c3b);
    k_sobel<<<dim3(16,16,16),256>>>();
    k_pts<<<NPTS/256,256>>>(rays_o,rays_d,viewdirs,w0,b0,w1,b1,w2,b2,w3,b3);
    k_render<<<NRAYS/8,256>>>(out);
}

// round 17
// speedup vs baseline: 1.1371x; 1.1371x over previous
#include <cuda_runtime.h>
#include <cuda_bf16.h>
#include <math.h>

#define NRAYS 1024
#define NSAMP 447
#define NPTS  (NRAYS*NSAMP)
#define NVOX  262144          // 64^3
#define NPAIR (NVOX/2)
#define NFINE 2097152         // 128^3
#define ACT_SHIFT (-9.210240366975184f)
#define BN_SCALE  (0.9999950000374997f)

typedef unsigned long long u64;
typedef unsigned int u32;

// ---------------- scratch (channel-major bf16x2 words: {voxA,voxB}) ----------------
__device__ u32 g_c1[64*NPAIR];    // x1 activations
__device__ u32 g_c2[64*NPAIR];    // x2 activations
__device__ u32 g_cg[16*NPAIR];    // bf16 copy of grid
__device__ float4 g_feat[(size_t)NFINE*4];
__device__ float  g_up0[NFINE];
__device__ float4 g_norm[NFINE];
__device__ float4 g_rgba[NPTS];
__device__ float4 g_nd4[NPTS];
__device__ float4 g_ns4[NPTS];
__device__ float  g_depth[NPTS];

// ---------------- f32x2 helpers ----------------
__device__ __forceinline__ u64 pk(float lo, float hi){
    u64 r; asm("mov.b64 %0,{%1,%2};" : "=l"(r) : "f"(lo), "f"(hi)); return r;
}
__device__ __forceinline__ u64 pk1(float v){ return pk(v,v); }
__device__ __forceinline__ float2 upk(u64 p){
    float2 r; asm("mov.b64 {%0,%1},%2;" : "=f"(r.x), "=f"(r.y) : "l"(p)); return r;
}
__device__ __forceinline__ void fma2(u64 &d, u64 a, u64 b){
    asm("fma.rn.f32x2 %0, %1, %2, %0;" : "+l"(d) : "l"(a), "l"(b));
}
__device__ __forceinline__ u32 bpack(float lo, float hi){
    __nv_bfloat162 h=__floats2bfloat162_rn(lo,hi); return *(u32*)&h;
}
// ---------------- cp.async ----------------
__device__ __forceinline__ void cpa16(u32 s, const void* g){
    asm volatile("cp.async.cg.shared.global [%0], [%1], 16;" :: "r"(s), "l"(g));
}
#define CPA_COMMIT() asm volatile("cp.async.commit_group;")
#define CPA_WAIT1()  asm volatile("cp.async.wait_group 1;" ::: "memory")
#define CPA_WAIT0()  asm volatile("cp.async.wait_group 0;" ::: "memory")
__device__ __forceinline__ u32 smem_u32(const void* p){
    u32 a; asm("{ .reg .u64 t; cvta.to.shared.u64 t, %1; cvt.u32.u64 %0, t; }" : "=r"(a) : "l"(p));
    return a;
}

// 16 output-pairs vs one input-channel pair (A0,A1 voxA; B0,B1 voxB)
#define CONVJ16(SWP) { \
    _Pragma("unroll") for(int o2=0;o2<16;o2++){ \
        ulonglong2 W=(SWP)[o2]; \
        fma2(aA[o2],A0,W.x); fma2(aA[o2],A1,W.y); \
        fma2(aB[o2],B0,W.x); fma2(aB[o2],B1,W.y); } }

// =============== K0: dummy (keeps ncu capture position) ===============
__global__ void k_dummy() {}

// =============== K1: x1 = prelu(bn(conv16->64)) -> g_c1 channel-major (+grid->g_cg) ===============
__global__ void __launch_bounds__(256,2) k_x1(const float* __restrict__ grid,
    const float* __restrict__ w, const float* __restrict__ b,
    const float* __restrict__ bg, const float* __restrict__ bb,
    const float* __restrict__ pa)
{
    __shared__ ulonglong2 sw[8*16];
    __shared__ __align__(16) float sin_[16*512];
    int t=threadIdx.x, ob=blockIdx.x, r0=ob*32;
    for(int i=t;i<8*16;i+=256){
        int cp=i>>4, o2=i&15;
        int ra=r0+2*o2, rb=ra+1;
        sw[i]=make_ulonglong2( pk(w[ra*16+2*cp],   w[rb*16+2*cp]),
                               pk(w[ra*16+2*cp+1], w[rb*16+2*cp+1]) );
    }
    size_t vbase=(size_t)blockIdx.y*512;
    u32 sb=smem_u32(sin_);
    for(int f=t; f<16*128; f+=256){
        int ch=f>>7, i16=f&127;
        cpa16(sb + ch*2048 + i16*16, grid + (size_t)ch*NVOX + vbase + i16*4);
    }
    CPA_COMMIT(); CPA_WAIT0();
    __syncthreads();

    int gid=blockIdx.y*256+t;
    u64 aA[16], aB[16];
#pragma unroll
    for(int o2=0;o2<16;o2++){ u64 bi=pk(__ldg(b+r0+2*o2),__ldg(b+r0+2*o2+1)); aA[o2]=bi; aB[o2]=bi; }
#pragma unroll
    for(int cp=0;cp<8;cp++){
        float2 i0=*(const float2*)(sin_+(2*cp  )*512+2*t);
        float2 i1=*(const float2*)(sin_+(2*cp+1)*512+2*t);
        if(ob==0){
            g_cg[(size_t)(2*cp  )*NPAIR+gid]=bpack(i0.x,i0.y);
            g_cg[(size_t)(2*cp+1)*NPAIR+gid]=bpack(i1.x,i1.y);
        }
        u64 A0=pk1(i0.x), A1=pk1(i1.x), B0=pk1(i0.y), B1=pk1(i1.y);
        CONVJ16(sw+cp*16);
    }
#pragma unroll
    for(int o2=0;o2<16;o2++){
        float2 yA=upk(aA[o2]), yB=upk(aB[o2]);
        int c0=r0+2*o2, c1=c0+1;
        float s0=BN_SCALE*__ldg(bg+c0), t0=__ldg(bb+c0), p0=__ldg(pa+c0);
        float s1=BN_SCALE*__ldg(bg+c1), t1=__ldg(bb+c1), p1=__ldg(pa+c1);
        float a0=yA.x*s0+t0, b0v=yB.x*s0+t0;
        float a1=yA.y*s1+t1, b1v=yB.y*s1+t1;
        a0=(a0>=0.f)?a0:p0*a0; b0v=(b0v>=0.f)?b0v:p0*b0v;
        a1=(a1>=0.f)?a1:p1*a1; b1v=(b1v>=0.f)?b1v:p1*b1v;
        g_c1[(size_t)c0*NPAIR+gid]=bpack(a0,b0v);
        g_c1[(size_t)c1*NPAIR+gid]=bpack(a1,b1v);
    }
}

// =============== K2: x2 conv 80->64 (32 outs/CTA), per-warp coalesced pipeline ===============
__global__ void __launch_bounds__(256,2) k_x2(
    const float* __restrict__ w, const float* __restrict__ b,
    const float* __restrict__ bg, const float* __restrict__ bb,
    const float* __restrict__ pa)
{
    __shared__ ulonglong2 sw[40*16];                  // 10 KB
    __shared__ __align__(16) u32 sbuf[8][3][8*32];    // 24 KB: [warp][stage][ch*32+pair]
    int t=threadIdx.x, ob=blockIdx.x, r0=ob*32;
    int wid=t>>5, lane=t&31;
    for(int i=t;i<40*16;i+=256){
        int cp=i>>4, o2=i&15;
        int ra=r0+2*o2, rb=ra+1;
        sw[i]=make_ulonglong2( pk(w[ra*80+2*cp],   w[rb*80+2*cp]),
                               pk(w[ra*80+2*cp+1], w[rb*80+2*cp+1]) );
    }
    __syncthreads();   // only CTA barrier

    size_t pb=(size_t)blockIdx.y*256 + wid*32;
    u32 swm=smem_u32(sbuf[wid]);

    #define X2_LOAD(c) { int st=(c)%3; u32 dst=swm+st*1024; \
        _Pragma("unroll") for(int q=0;q<2;q++){ \
            int idx=q*32+lane; int chl=idx>>3, sub=idx&7; \
            int g=(c)*8+chl; \
            const u32* S=(g<64)?(g_c1+(size_t)g*NPAIR):(g_cg+(size_t)(g-64)*NPAIR); \
            cpa16(dst+chl*128+sub*16, S+pb+sub*4); \
        } CPA_COMMIT(); }

    X2_LOAD(0); X2_LOAD(1);

    u64 aA[16], aB[16];
#pragma unroll
    for(int o2=0;o2<16;o2++){ u64 bi=pk(__ldg(b+r0+2*o2),__ldg(b+r0+2*o2+1)); aA[o2]=bi; aB[o2]=bi; }

    for(int c=0;c<10;c++){
        CPA_WAIT1();
        __syncwarp();
        if(c+2<10){ X2_LOAD(c+2); } else { CPA_COMMIT(); }
        const u32* slice=sbuf[wid][c%3];
#pragma unroll
        for(int j=0;j<4;j++){
            u32 w0=slice[(2*j  )*32+lane];
            u32 w1=slice[(2*j+1)*32+lane];
            u64 A0=pk1(__uint_as_float(w0<<16));
            u64 B0=pk1(__uint_as_float(w0&0xffff0000u));
            u64 A1=pk1(__uint_as_float(w1<<16));
            u64 B1=pk1(__uint_as_float(w1&0xffff0000u));
            CONVJ16(sw+(c*4+j)*16);
        }
    }
    size_t gid=pb+lane;
#pragma unroll
    for(int o2=0;o2<16;o2++){
        float2 yA=upk(aA[o2]), yB=upk(aB[o2]);
        int c0=r0+2*o2, c1=c0+1;
        float s0=BN_SCALE*__ldg(bg+c0), t0=__ldg(bb+c0), p0=__ldg(pa+c0);
        float s1=BN_SCALE*__ldg(bg+c1), t1=__ldg(bb+c1), p1=__ldg(pa+c1);
        float a0=yA.x*s0+t0, b0v=yB.x*s0+t0;
        float a1=yA.y*s1+t1, b1v=yB.y*s1+t1;
        a0=(a0>=0.f)?a0:p0*a0; b0v=(b0v>=0.f)?b0v:p0*b0v;
        a1=(a1>=0.f)?a1:p1*a1; b1v=(b1v>=0.f)?b1v:p1*b1v;
        g_c2[(size_t)c0*NPAIR+gid]=bpack(a0,b0v);
        g_c2[(size_t)c1*NPAIR+gid]=bpack(a1,b1v);
    }
}

// =============== K3: x3 conv 144->128 (32 outs/CTA), per-warp pipeline + pixel-shuffle ===============
__global__ void __launch_bounds__(256,2) k_x3(
    const float* __restrict__ w, const float* __restrict__ b)
{
    __shared__ ulonglong2 sw[72*16];                  // 18 KB
    __shared__ __align__(16) u32 sbuf[8][3][8*32];    // 24 KB
    int t=threadIdx.x, ob=blockIdx.x, r0=ob*32;
    int wid=t>>5, lane=t&31;
    for(int i=t;i<72*16;i+=256){
        int cp=i>>4, o2=i&15;
        int ra=r0+2*o2, rb=ra+1;
        sw[i]=make_ulonglong2( pk(w[ra*144+2*cp],   w[rb*144+2*cp]),
                               pk(w[ra*144+2*cp+1], w[rb*144+2*cp+1]) );
    }
    __syncthreads();

    size_t pb=(size_t)blockIdx.y*256 + wid*32;
    u32 swm=smem_u32(sbuf[wid]);

    #define X3_LOAD(c) { int st=(c)%3; u32 dst=swm+st*1024; \
        _Pragma("unroll") for(int q=0;q<2;q++){ \
            int idx=q*32+lane; int chl=idx>>3, sub=idx&7; \
            int g=(c)*8+chl; \
            const u32* S=(g<64)?(g_c1+(size_t)g*NPAIR) \
                        :(g<128)?(g_c2+(size_t)(g-64)*NPAIR) \
                        :(g_cg+(size_t)(g-128)*NPAIR); \
            cpa16(dst+chl*128+sub*16, S+pb+sub*4); \
        } CPA_COMMIT(); }

    X3_LOAD(0); X3_LOAD(1);

    u64 aA[16], aB[16];
#pragma unroll
    for(int o2=0;o2<16;o2++){ u64 bi=pk(__ldg(b+r0+2*o2),__ldg(b+r0+2*o2+1)); aA[o2]=bi; aB[o2]=bi; }

    for(int c=0;c<18;c++){
        CPA_WAIT1();
        __syncwarp();
        if(c+2<18){ X3_LOAD(c+2); } else { CPA_COMMIT(); }
        const u32* slice=sbuf[wid][c%3];
#pragma unroll
        for(int j=0;j<4;j++){
            u32 w0=slice[(2*j  )*32+lane];
            u32 w1=slice[(2*j+1)*32+lane];
            u64 A0=pk1(__uint_as_float(w0<<16));
            u64 B0=pk1(__uint_as_float(w0&0xffff0000u));
            u64 A1=pk1(__uint_as_float(w1<<16));
            u64 B1=pk1(__uint_as_float(w1&0xffff0000u));
            CONVJ16(sw+(c*4+j)*16);
        }
    }
    // unpack + pixel-shuffle: channels r0..r0+31 -> latents ob*4..ob*4+3, q=ob
    float accA[32], accB[32];
#pragma unroll
    for(int o2=0;o2<16;o2++){
        float2 fA=upk(aA[o2]), fB=upk(aB[o2]);
        accA[2*o2]=fA.x; accA[2*o2+1]=fA.y;
        accB[2*o2]=fB.x; accB[2*o2+1]=fB.y;
    }
    int gid=(int)(pb+lane);
#pragma unroll
    for(int half=0; half<2; half++){
        const float* acc = half? accB : accA;
        int v = 2*gid + half;
        int x=v>>12, y=(v>>6)&63, z=v&63;
#pragma unroll
        for(int s=0;s<8;s++){
            g_feat[(size_t)v*32 + s*4 + ob] =
                make_float4(acc[0*8+s],acc[1*8+s],acc[2*8+s],acc[3*8+s]);
            if(ob==0){
                int X=2*x+((s>>2)&1), Y=2*y+((s>>1)&1), Z=2*z+(s&1);
                g_up0[((size_t)X*128+Y)*128+Z]=acc[s];
            }
        }
    }
}

// =============== K4: separable Sobel -> normals ===============
__global__ void __launch_bounds__(256) k_sobel()
{
    __shared__ float sm[1728];
    __shared__ float A[1152], Bz[1152];
    __shared__ float C[768], D[768], E[768];
    const float HH[5]={1.f,4.f,6.f,4.f,1.f};
    const float HD[5]={-1.f,-2.f,0.f,2.f,1.f};
    int bx=blockIdx.x*8, by=blockIdx.y*8, bz=blockIdx.z*8;
    int t=threadIdx.x;
    for(int i=t;i<1728;i+=256){
        int a=i/144, b=(i/12)%12, c=i%12;
        int X=bx+a-2, Y=by+b-2, Z=bz+c-2;
        float val=0.f;
        if(X>=0&&X<128&&Y>=0&&Y<128&&Z>=0&&Z<128) val=g_up0[((size_t)X*128+Y)*128+Z];
        sm[i]=val;
    }
    __syncthreads();
    for(int i=t;i<1152;i+=256){
        int a=i/96, b=(i/8)%12, zo=i&7;
        const float* base=&sm[(a*12+b)*12+zo];
        float s=0.f,d=0.f;
#pragma unroll
        for(int k=0;k<5;k++){ float v=base[k]; s=fmaf(HH[k],v,s); d=fmaf(HD[k],v,d); }
        A[i]=s; Bz[i]=d;
    }
    __syncthreads();
    for(int i=t;i<768;i+=256){
        int a=i>>6, yo=(i>>3)&7, zo=i&7;
        float c=0.f,dd=0.f,e=0.f;
#pragma unroll
        for(int j=0;j<5;j++){
            int idx=(a*12+yo+j)*8+zo;
            float av=A[idx], bv=Bz[idx];
            c=fmaf(HH[j],av,c); dd=fmaf(HD[j],av,dd); e=fmaf(HH[j],bv,e);
        }
        C[i]=c; D[i]=dd; E[i]=e;
    }
    __syncthreads();
    for(int i=t;i<512;i+=256){
        int xo=i>>6, yo=(i>>3)&7, zo=i&7;
        float sx=0.f,sy=0.f,sz=0.f;
#pragma unroll
        for(int k=0;k<5;k++){
            int idx=((xo+k)*8+yo)*8+zo;
            sx=fmaf(HD[k],C[idx],sx); sy=fmaf(HH[k],D[idx],sy); sz=fmaf(HH[k],E[idx],sz);
        }
        float l=sqrtf(sx*sx+sy*sy+sz*sz);
        float r=1.f/fmaxf(l,1e-12f);
        g_norm[(((size_t)(bx+xo)*128)+(by+yo))*128+(bz+zo)] =
            make_float4(-sx*r,-sy*r,-sz*r,0.f);
    }
}

// =============== K5: per-sample point shading ===============
#define FEED0(cp, v0, v1) { u64 x0=pk1(v0), x1=pk1(v1); \
    _Pragma("unroll") for(int o2=0;o2<32;o2++){ ulonglong2 W=SW0[(cp)*32+o2]; \
        fma2(h2[o2],x0,W.x); fma2(h2[o2],x1,W.y);} }

__global__ void __launch_bounds__(256) k_pts(
    const float* __restrict__ rays_o, const float* __restrict__ rays_d,
    const float* __restrict__ viewdirs,
    const float* __restrict__ w0,const float* __restrict__ b0,
    const float* __restrict__ w1,const float* __restrict__ b1,
    const float* __restrict__ w2,const float* __restrict__ b2,
    const float* __restrict__ w3,const float* __restrict__ b3)
{
    __shared__ ulonglong2 SW0[27*32];
    __shared__ ulonglong2 SW1[32*32];
    __shared__ ulonglong2 SW2[32*32];
    __shared__ u64 PB0[32], PB1[32], PB2[32];
    __shared__ float SW3[192], PB3[3];
    int t=threadIdx.x;
    for(int i=t;i<27*32;i+=256){ int cp=i>>5,o2=i&31;
        SW0[i]=make_ulonglong2( pk(w0[(2*cp)*64+2*o2],   w0[(2*cp)*64+2*o2+1]),
                                pk(w0[(2*cp+1)*64+2*o2], w0[(2*cp+1)*64+2*o2+1]) ); }
    for(int i=t;i<32*32;i+=256){ int cp=i>>5,o2=i&31;
        SW1[i]=make_ulonglong2( pk(w1[(2*cp)*64+2*o2],   w1[(2*cp)*64+2*o2+1]),
                                pk(w1[(2*cp+1)*64+2*o2], w1[(2*cp+1)*64+2*o2+1]) );
        SW2[i]=make_ulonglong2( pk(w2[(2*cp)*64+2*o2],   w2[(2*cp)*64+2*o2+1]),
                                pk(w2[(2*cp+1)*64+2*o2], w2[(2*cp+1)*64+2*o2+1]) ); }
    if(t<32){ PB0[t]=pk(b0[2*t],b0[2*t+1]); PB1[t]=pk(b1[2*t],b1[2*t+1]); PB2[t]=pk(b2[2*t],b2[2*t+1]); }
    for(int i=t;i<192;i+=256) SW3[i]=w3[i];
    if(t<3) PB3[t]=b3[t];
    __syncthreads();

    int tid = blockIdx.x*256+t;
    int ray = tid/NSAMP, s = tid - ray*NSAMP;
    float ox=rays_o[ray*3+0], oy=rays_o[ray*3+1], oz=rays_o[ray*3+2];
    float dx=rays_d[ray*3+0], dy=rays_d[ray*3+1], dz=rays_d[ray*3+2];

    float ex=(dx==0.f)?1e-6f:dx, ey=(dy==0.f)?1e-6f:dy, ez=(dz==0.f)?1e-6f:dz;
    float rax=(1.f-ox)/ex, rbx=(-1.f-ox)/ex;
    float ray_=(1.f-oy)/ey, rby=(-1.f-oy)/ey;
    float raz=(1.f-oz)/ez, rbz=(-1.f-oz)/ez;
    float tmin=fmaxf(fmaxf(fminf(rax,rbx),fminf(ray_,rby)),fminf(raz,rbz));
    float tmax=fminf(fminf(fmaxf(rax,rbx),fmaxf(ray_,rby)),fmaxf(raz,rbz));
    tmin=fminf(fmaxf(tmin,0.2f),6.f);
    tmax=fminf(fmaxf(tmax,0.2f),6.f);
    bool maskray = (tmax<=tmin);
    float dnorm=sqrtf(dx*dx+dy*dy+dz*dz);
    float interpx = tmin + (0.015625f*(float)s)/dnorm;
    float px=ox+dx*interpx, py=oy+dy*interpx, pz=oz+dz*interpx;
    g_depth[tid]=dnorm*interpx;

    bool inside = !maskray && !(px<-1.f||px>1.f) && !(py<-1.f||py>1.f) && !(pz<-1.f||pz>1.f);
    if(!inside){
        float4 z4=make_float4(0.f,0.f,0.f,0.f);
        g_rgba[tid]=z4; g_nd4[tid]=z4; g_ns4[tid]=z4;
        return;
    }

    float u0=fminf(fmaxf((px+1.f)*63.5f,0.f),127.f);
    float u1=fminf(fmaxf((py+1.f)*63.5f,0.f),127.f);
    float u2=fminf(fmaxf((pz+1.f)*63.5f,0.f),127.f);
    int ix=min((int)floorf(u0),126), iy=min((int)floorf(u1),126), iz=min((int)floorf(u2),126);
    float fx=u0-ix, fy=u1-iy, fz=u2-iz;
    float wx[2]={1.f-fx,fx}, wy[2]={1.f-fy,fy}, wz[2]={1.f-fz,fz};

    float feat[16];
#pragma unroll
    for(int c=0;c<16;c++) feat[c]=0.f;
    float c0a[2][2][2];
    float nx=0,ny=0,nz=0;
#pragma unroll
    for(int a=0;a<2;a++)
#pragma unroll
    for(int b_=0;b_<2;b_++)
#pragma unroll
    for(int c=0;c<2;c++){
        int X=ix+a, Y=iy+b_, Z=iz+c;
        float w = wx[a]*wy[b_]*wz[c];
        size_t coarse = ((size_t)(X>>1)*64+(Y>>1))*64+(Z>>1);
        size_t base4 = (coarse*8 + ((X&1)*4+(Y&1)*2+(Z&1)))*4;
        float4 q0=g_feat[base4+0], q1=g_feat[base4+1], q2=g_feat[base4+2], q3=g_feat[base4+3];
        feat[0]+=w*q0.x; feat[1]+=w*q0.y; feat[2]+=w*q0.z; feat[3]+=w*q0.w;
        feat[4]+=w*q1.x; feat[5]+=w*q1.y; feat[6]+=w*q1.z; feat[7]+=w*q1.w;
        feat[8]+=w*q2.x; feat[9]+=w*q2.y; feat[10]+=w*q2.z; feat[11]+=w*q2.w;
        feat[12]+=w*q3.x; feat[13]+=w*q3.y; feat[14]+=w*q3.z; feat[15]+=w*q3.w;
        c0a[a][b_][c]=q0.x;
        float4 nn = g_norm[((size_t)X*128+Y)*128+Z];
        nx+=w*nn.x; ny+=w*nn.y; nz+=w*nn.z;
    }
    float gx=0,gy=0,gz=0;
#pragma unroll
    for(int b_=0;b_<2;b_++)
#pragma unroll
    for(int c=0;c<2;c++) gx += wy[b_]*wz[c]*(c0a[1][b_][c]-c0a[0][b_][c]);
#pragma unroll
    for(int a=0;a<2;a++)
#pragma unroll
    for(int c=0;c<2;c++) gy += wx[a]*wz[c]*(c0a[a][1][c]-c0a[a][0][c]);
#pragma unroll
    for(int a=0;a<2;a++)
#pragma unroll
    for(int b_=0;b_<2;b_++) gz += wx[a]*wy[b_]*(c0a[a][b_][1]-c0a[a][b_][0]);

    float d0=feat[0];
    float xs=d0+ACT_SHIFT;
    float ex_=expf(xs);
    float sp=log1pf(ex_);
    float alpha=1.f-expf(-sp*0.5f);
    float sig=ex_/(1.f+ex_);
    float k = 0.5f*expf(-0.5f*sp)*sig*63.5f;
    gx*=k; gy*=k; gz*=k;
    float gl=sqrtf(gx*gx+gy*gy+gz*gz);
    float gr=1.f/fmaxf(gl,1e-12f);
    float ndx=-gx*gr, ndy=-gy*gr, ndz=-gz*gr;
    float nl=sqrtf(nx*nx+ny*ny+nz*nz);
    float nr=1.f/fmaxf(nl,1e-12f);
    g_ns4[tid]=make_float4(-nx*nr,-ny*nr,-nz*nr,0.f);
    g_nd4[tid]=make_float4(ndx,ndy,ndz,0.f);

    float vx=viewdirs[ray*3+0], vy=viewdirs[ray*3+1], vz=viewdirs[ray*3+2];
    float dot = -(vx*ndx+vy*ndy+vz*ndz);
    float rx=2.f*dot*ndx+vx, ry=2.f*dot*ndy+vy, rz=2.f*dot*ndz+vz;

    u64 h2[32];
#pragma unroll
    for(int o2=0;o2<32;o2++) h2[o2]=PB0[o2];
#pragma unroll
    for(int cp=0;cp<7;cp++){ FEED0(cp, feat[2*cp+1], feat[2*cp+2]); }
    FEED0(7, feat[15], rx);
    FEED0(8, ry, rz);
#pragma unroll
    for(int q=0;q<6;q++){
        float fr=(float)(1<<q);
        float s0,c0_,s1,c1,s2,c2;
        __sincosf(rx*fr,&s0,&c0_); __sincosf(ry*fr,&s1,&c1); __sincosf(rz*fr,&s2,&c2);
        FEED0(9+3*q,  s0, s1);
        FEED0(10+3*q, s2, c0_);
        FEED0(11+3*q, c1, c2);
    }
    float h[64];
#pragma unroll
    for(int o2=0;o2<32;o2++){ float2 f=upk(h2[o2]); h[2*o2]=fmaxf(f.x,0.f); h[2*o2+1]=fmaxf(f.y,0.f); }

#pragma unroll
    for(int o2=0;o2<32;o2++) h2[o2]=PB1[o2];
#pragma unroll 2
    for(int cp=0;cp<32;cp++){
        u64 x0=pk1(h[2*cp]), x1=pk1(h[2*cp+1]);
#pragma unroll
        for(int o2=0;o2<32;o2++){ ulonglong2 W=SW1[cp*32+o2]; fma2(h2[o2],x0,W.x); fma2(h2[o2],x1,W.y); }
    }
#pragma unroll
    for(int o2=0;o2<32;o2++){ float2 f=upk(h2[o2]); h[2*o2]=fmaxf(f.x,0.f); h[2*o2+1]=fmaxf(f.y,0.f); }

#pragma unroll
    for(int o2=0;o2<32;o2++) h2[o2]=PB2[o2];
#pragma unroll 2
    for(int cp=0;cp<32;cp++){
        u64 x0=pk1(h[2*cp]), x1=pk1(h[2*cp+1]);
#pragma unroll
        for(int o2=0;o2<32;o2++){ ulonglong2 W=SW2[cp*32+o2]; fma2(h2[o2],x0,W.x); fma2(h2[o2],x1,W.y); }
    }
#pragma unroll
    for(int o2=0;o2<32;o2++){ float2 f=upk(h2[o2]); h[2*o2]=fmaxf(f.x,0.f); h[2*o2+1]=fmaxf(f.y,0.f); }

    float r0=PB3[0], r1=PB3[1], r2=PB3[2];
#pragma unroll
    for(int i=0;i<64;i++){
        float hv=h[i];
        r0=fmaf(hv,SW3[i*3+0],r0); r1=fmaf(hv,SW3[i*3+1],r1); r2=fmaf(hv,SW3[i*3+2],r2);
    }
    g_rgba[tid]=make_float4(1.f/(1.f+expf(-r0)), 1.f/(1.f+expf(-r1)),
                            1.f/(1.f+expf(-r2)), alpha);
}

// =============== K6: per-ray volumetric render (warp per ray) ===============
__global__ void __launch_bounds__(256) k_render(float* __restrict__ out)
{
    int warp=(blockIdx.x*blockDim.x+threadIdx.x)>>5;
    int lane=threadIdx.x&31;
    if(warp>=NRAYS) return;
    int base=warp*NSAMP;
    float T=1.f;
    float sr=0,sg=0,sb=0,sd=0,sa=0,n0=0,n1=0,n2=0,m0=0,m1=0,m2=0;
    for(int c=0;c<14;c++){
        int s=c*32+lane;
        bool val=(s<NSAMP);
        int idx=base+(val?s:0);
        float4 rgba = g_rgba[idx];
        float a = val? rgba.w : 0.f;
        float p=fmaxf(1.f-a,1e-10f);
        float incl=p;
#pragma unroll
        for(int off=1;off<32;off<<=1){
            float tt=__shfl_up_sync(0xffffffffu,incl,off);
            if(lane>=off) incl*=tt;
        }
        float excl=__shfl_up_sync(0xffffffffu,incl,1);
        if(lane==0) excl=1.f;
        float w=a*T*excl;
        float4 nd=g_nd4[idx], ns=g_ns4[idx];
        sr=fmaf(w,rgba.x,sr); sg=fmaf(w,rgba.y,sg); sb=fmaf(w,rgba.z,sb);
        sd=fmaf(w,g_depth[idx],sd);  sa+=w;
        n0=fmaf(w,nd.x,n0); n1=fmaf(w,nd.y,n1); n2=fmaf(w,nd.z,n2);
        m0=fmaf(w,ns.x,m0); m1=fmaf(w,ns.y,m1); m2=fmaf(w,ns.z,m2);
        T*=__shfl_sync(0xffffffffu,incl,31);
    }
#pragma unroll
    for(int off=16;off>0;off>>=1){
        sr+=__shfl_xor_sync(0xffffffffu,sr,off); sg+=__shfl_xor_sync(0xffffffffu,sg,off);
        sb+=__shfl_xor_sync(0xffffffffu,sb,off); sd+=__shfl_xor_sync(0xffffffffu,sd,off);
        sa+=__shfl_xor_sync(0xffffffffu,sa,off);
        n0+=__shfl_xor_sync(0xffffffffu,n0,off); n1+=__shfl_xor_sync(0xffffffffu,n1,off);
        n2+=__shfl_xor_sync(0xffffffffu,n2,off);
        m0+=__shfl_xor_sync(0xffffffffu,m0,off); m1+=__shfl_xor_sync(0xffffffffu,m1,off);
        m2+=__shfl_xor_sync(0xffffffffu,m2,off);
    }
    if(lane==0){
        float* o=out+(size_t)warp*12;
        float dm = sd + T*6.f;
        o[0]=sr+T; o[1]=sg+T; o[2]=sb+T;
        o[3]=dm; o[4]=1.f/dm; o[5]=sa;
        o[6]=n0; o[7]=n1; o[8]=n2;
        o[9]=m0; o[10]=m1; o[11]=m2;
    }
}

extern "C" void kernel_launch(void* const* d_in, const int* in_sizes, int n_in,
                              void* d_out, int out_size)
{
    const float* rays_o  =(const float*)d_in[0];
    const float* rays_d  =(const float*)d_in[1];
    const float* viewdirs=(const float*)d_in[2];
    const float* grid    =(const float*)d_in[3];
    const float* c1w=(const float*)d_in[4];  const float* c1b=(const float*)d_in[5];
    const float* bn1g=(const float*)d_in[6]; const float* bn1b=(const float*)d_in[7];
    const float* pr1a=(const float*)d_in[8];
    const float* c2w=(const float*)d_in[9];  const float* c2b=(const float*)d_in[10];
    const float* bn2g=(const float*)d_in[11];const float* bn2b=(const float*)d_in[12];
    const float* pr2a=(const float*)d_in[13];
    const float* c3w=(const float*)d_in[14]; const float* c3b=(const float*)d_in[15];
    const float* w0=(const float*)d_in[16];  const float* b0=(const float*)d_in[17];
    const float* w1=(const float*)d_in[18];  const float* b1=(const float*)d_in[19];
    const float* w2=(const float*)d_in[20];  const float* b2=(const float*)d_in[21];
    const float* w3=(const float*)d_in[22];  const float* b3=(const float*)d_in[23];
    float* out=(float*)d_out;

    k_dummy<<<1,32>>>();
    k_x1<<<dim3(2,512),256>>>(grid,c1w,c1b,bn1g,bn1b,pr1a);
    k_x2<<<dim3(2,512),256>>>(c2w,c2b,bn2g,bn2b,pr2a);
    k_x3<<<dim3(4,512),256>>>(c3w,c3b);
    k_sobel<<<dim3(16,16,16),256>>>();
    k_pts<<<NPTS/256,256>>>(rays_o,rays_d,viewdirs,w0,b0,w1,b1,w2,b2,w3,b3);
    k_render<<<NRAYS/8,256>>>(out);
}